// round 4
// baseline (speedup 1.0000x reference)
#include <cuda_runtime.h>
#include <cuda_bf16.h>
#include <math.h>

// Problem constants
#define BB   64     // batch
#define TT   512    // time
#define EE   256    // embedding
#define HH   256    // hidden
#define G4   1024   // 4*H
#define KK   10     // tags

// -------- device scratch (allocation-free rule: static device globals) -----
__device__ float g_pre[2u * 32768u * 1024u];          // [dir][m=t*64+b][4H]
__device__ float g_h[2u * 512u * 64u * 256u];         // [dir][t][b][h]
__device__ float g_logits[512u * 64u * 10u];          // [t][b][k]
__device__ unsigned g_bar;

__global__ void init_kernel() { g_bar = 0u; }

// -------- f32x2 packed helpers (Blackwell FFMA2) ----------------------------
__device__ __forceinline__ unsigned long long pk2(float x, float y) {
    unsigned long long r;
    asm("mov.b64 %0, {%1,%2};" : "=l"(r) : "f"(x), "f"(y));
    return r;
}
__device__ __forceinline__ void fma2(unsigned long long& d,
                                     unsigned long long a,
                                     unsigned long long b) {
    asm("fma.rn.f32x2 %0, %1, %2, %0;" : "+l"(d) : "l"(a), "l"(b));
}
__device__ __forceinline__ float2 up2(unsigned long long v) {
    float2 r;
    asm("mov.b64 {%0,%1}, %2;" : "=f"(r.x), "=f"(r.y) : "l"(v));
    return r;
}

// ---------------------------------------------------------------------------
// Kernel A: fused embedding-gather + GEMM:  g_pre = emb[sent] @ Wih^T + bias
// grid (16, 512, 2). FFMA2 inner product, acc packed over n-pairs.
// ---------------------------------------------------------------------------
__global__ void pregemm_kernel(const int* __restrict__ sent,
                               const float* __restrict__ emb,
                               const float* __restrict__ Wih_f,
                               const float* __restrict__ b_f,
                               const float* __restrict__ Wih_b,
                               const float* __restrict__ b_b) {
    const int dir = blockIdx.z;
    const int t   = blockIdx.y;
    const int n0  = blockIdx.x * 64;
    const float* Wih  = dir ? Wih_b : Wih_f;
    const float* bias = dir ? b_b  : b_f;

    __shared__ float As[16][68];
    __shared__ float Bs[16][68];
    __shared__ int   toks[64];

    const int tid = threadIdx.x;          // 256 threads
    if (tid < 64) toks[tid] = sent[tid * TT + t];
    __syncthreads();

    const int mL = tid >> 2;
    const int kq = tid & 3;
    const int ty = tid >> 4;
    const int tx = tid & 15;

    unsigned long long acc[4][2];
#pragma unroll
    for (int i = 0; i < 4; ++i) { acc[i][0] = 0ull; acc[i][1] = 0ull; }

    const float4* emb4 = (const float4*)emb;
    const float4* w4   = (const float4*)Wih;

    for (int k0 = 0; k0 < 256; k0 += 16) {
        float4 av = emb4[(size_t)toks[mL] * 64 + (k0 >> 2) + kq];
        float4 bv = w4[(size_t)(n0 + mL) * 64 + (k0 >> 2) + kq];
        __syncthreads();
        As[kq * 4 + 0][mL] = av.x;  As[kq * 4 + 1][mL] = av.y;
        As[kq * 4 + 2][mL] = av.z;  As[kq * 4 + 3][mL] = av.w;
        Bs[kq * 4 + 0][mL] = bv.x;  Bs[kq * 4 + 1][mL] = bv.y;
        Bs[kq * 4 + 2][mL] = bv.z;  Bs[kq * 4 + 3][mL] = bv.w;
        __syncthreads();
#pragma unroll
        for (int kk = 0; kk < 16; ++kk) {
            float4 a = *(const float4*)&As[kk][ty * 4];
            unsigned long long b01 = *(const unsigned long long*)&Bs[kk][tx * 4];
            unsigned long long b23 = *(const unsigned long long*)&Bs[kk][tx * 4 + 2];
            unsigned long long a0 = pk2(a.x, a.x);
            unsigned long long a1 = pk2(a.y, a.y);
            unsigned long long a2 = pk2(a.z, a.z);
            unsigned long long a3 = pk2(a.w, a.w);
            fma2(acc[0][0], a0, b01); fma2(acc[0][1], a0, b23);
            fma2(acc[1][0], a1, b01); fma2(acc[1][1], a1, b23);
            fma2(acc[2][0], a2, b01); fma2(acc[2][1], a2, b23);
            fma2(acc[3][0], a3, b01); fma2(acc[3][1], a3, b23);
        }
    }

    float4 bvv = ((const float4*)bias)[(n0 >> 2) + tx];
    float4* out4 = (float4*)g_pre;
#pragma unroll
    for (int i = 0; i < 4; ++i) {
        int b = ty * 4 + i;
        float2 p0 = up2(acc[i][0]);
        float2 p1 = up2(acc[i][1]);
        float4 o;
        o.x = p0.x + bvv.x; o.y = p0.y + bvv.y;
        o.z = p1.x + bvv.z; o.w = p1.y + bvv.w;
        out4[((size_t)dir * 32768 + (size_t)t * 64 + b) * 256 + (n0 >> 2) + tx] = o;
    }
}

// ---------------------------------------------------------------------------
// Kernel B: persistent recurrence. 128 blocks = 2 dirs x 64 slices (4 units).
// Thread map: u = tid&3, b = tid>>2.  FFMA2 with k-parity packing.
// smem (floats):
//   sW  : float4[4u][257]  (pitch 257 f4 -> per-u 16B skew; [g*64+k4])  4112 f
//   sHT : [64 b][260]      (padded h rows; f4 conflict-free)           16640 f
//   sGP : [64 b][17]                                                    1088 f
// ---------------------------------------------------------------------------
#define OFF_HT 4112
#define OFF_GP (4112 + 16640)
#define REC_SMEM_FLOATS (4112 + 16640 + 1088)

__device__ __forceinline__ float sigm(float x) { return 1.f / (1.f + expf(-x)); }

__global__ void lstm_rec_kernel(const float* __restrict__ Whh_f,
                                const float* __restrict__ Whh_b) {
    const int bid   = blockIdx.x;
    const int dir   = bid >> 6;
    const int slice = bid & 63;
    const int hu0   = slice * 4;
    const int tid   = threadIdx.x;        // 256
    const int u     = tid & 3;
    const int b     = tid >> 2;

    const float* Whh = dir ? Whh_b : Whh_f;

    extern __shared__ float sm[];
    float4* sW4 = (float4*)sm;
    float*  sHT = sm + OFF_HT;
    float*  sGP = sm + OFF_GP;

    // Whh -> sW[u][g][k4]
    const float4* whh4 = (const float4*)Whh;
    for (int e = tid; e < 1024; e += 256) {
        int uu = e >> 8, rem = e & 255, g = rem >> 6, k4 = rem & 63;
        sW4[uu * 257 + g * 64 + k4] = whh4[(size_t)(g * 256 + hu0 + uu) * 64 + k4];
    }

    const float4* gp4 = (const float4*)g_pre;
    const float4* gh4 = (const float4*)g_h;

    // stage g_pre for t0
    {
        const int t0 = dir ? 511 : 0;
        int bb = tid >> 2, g = tid & 3;
        float4 v = __ldcg(&gp4[((size_t)dir * 32768 + (size_t)t0 * 64 + bb) * 256 + g * 64 + slice]);
        float* d = &sGP[bb * 17 + g * 4];
        d[0] = v.x; d[1] = v.y; d[2] = v.z; d[3] = v.w;
    }

    const ulonglong2* hrow = (const ulonglong2*)(sHT + b * 260);
    const ulonglong2* wu   = ((const ulonglong2*)sm) + u * 257;

    float c = 0.f;

    for (int it = 0; it < 512; ++it) {
        const int t = dir ? (511 - it) : it;

        // stage previous h into sHT[b][k] (g_h layout [dir][t][b][h])
        if (it == 0) {
            float4 z = make_float4(0.f, 0.f, 0.f, 0.f);
            for (int e = tid; e < 4096; e += 256) {
                int b_ = e >> 6, k4 = e & 63;
                *(float4*)(sHT + b_ * 260 + k4 * 4) = z;
            }
        } else {
            const int tp = dir ? (t + 1) : (t - 1);
            size_t base = ((size_t)(dir * 512 + tp)) * 4096;
            for (int e = tid; e < 4096; e += 256) {
                int b_ = e >> 6, k4 = e & 63;
                *(float4*)(sHT + b_ * 260 + k4 * 4) = __ldcg(&gh4[base + e]);
            }
        }
        __syncthreads();

        unsigned long long acc0 = pk2(sGP[b * 17 + 0 + u], 0.f);
        unsigned long long acc1 = pk2(sGP[b * 17 + 4 + u], 0.f);
        unsigned long long acc2 = pk2(sGP[b * 17 + 8 + u], 0.f);
        unsigned long long acc3 = pk2(sGP[b * 17 + 12 + u], 0.f);

#pragma unroll 8
        for (int k4 = 0; k4 < 64; ++k4) {
            ulonglong2 h2 = hrow[k4];
            ulonglong2 w;
            w = wu[0 * 64 + k4]; fma2(acc0, w.x, h2.x); fma2(acc0, w.y, h2.y);
            w = wu[1 * 64 + k4]; fma2(acc1, w.x, h2.x); fma2(acc1, w.y, h2.y);
            w = wu[2 * 64 + k4]; fma2(acc2, w.x, h2.x); fma2(acc2, w.y, h2.y);
            w = wu[3 * 64 + k4]; fma2(acc3, w.x, h2.x); fma2(acc3, w.y, h2.y);
        }

        float2 p;
        p = up2(acc0); float a0 = p.x + p.y;
        p = up2(acc1); float a1 = p.x + p.y;
        p = up2(acc2); float a2 = p.x + p.y;
        p = up2(acc3); float a3 = p.x + p.y;

        float iv = sigm(a0), fv = sigm(a1), gv = tanhf(a2), ov = sigm(a3);
        c = fv * c + iv * gv;
        float hval = ov * tanhf(c);
        // [dir][t][b][h]; per-warp writes are 16B-contiguous per batch
        g_h[(((size_t)(dir * 512 + t)) * 64 + b) * 256 + hu0 + u] = hval;

        __syncthreads();   // everyone done reading sGP/sHT

        // stage g_pre for next step (overlaps with barrier wait)
        if (it < 511) {
            const int tn = dir ? (t - 1) : (t + 1);
            int bb = tid >> 2, g = tid & 3;
            float4 v = __ldcg(&gp4[((size_t)dir * 32768 + (size_t)tn * 64 + bb) * 256 + g * 64 + slice]);
            float* d = &sGP[bb * 17 + g * 4];
            d[0] = v.x; d[1] = v.y; d[2] = v.z; d[3] = v.w;

            if (tid == 0) {
                __threadfence();
                atomicAdd(&g_bar, 1u);
                unsigned target = 128u * (unsigned)(it + 1);
                volatile unsigned* vb = &g_bar;
                while (*vb < target) { }
            }
            __syncthreads();
            __threadfence();
        }
    }
}

// ---------------------------------------------------------------------------
// Kernel C: logits = concat(h_f, h_b) @ W_out^T + b_out.  grid 512(t), 640 thr
// g_h layout is [dir][t][b][h]; transpose chunks into sCH[r][b] (pitch 65).
// ---------------------------------------------------------------------------
__global__ void logits_kernel(const float* __restrict__ Wout,
                              const float* __restrict__ bout) {
    const int t = blockIdx.x;
    __shared__ float sWo[10 * 512];   // 20KB
    __shared__ float sCH[64 * 65];    // 16.6KB
    __shared__ float sBo[10];

    const int tid = threadIdx.x;      // 640
    for (int idx = tid; idx < 5120; idx += 640) sWo[idx] = Wout[idx];
    if (tid < 10) sBo[tid] = bout[tid];

    const int n = tid / 64, bb = tid & 63;
    float acc = 0.f;
    const float4* gh4 = (const float4*)g_h;

    for (int ch = 0; ch < 8; ++ch) {
        __syncthreads();
        for (int idx = tid; idx < 1024; idx += 640) {
            int b_ = idx >> 4, q = idx & 15;
            int d = ch >> 2;
            int hid4 = (ch & 3) * 16 + q;
            float4 v = gh4[(((size_t)d * 512 + t) * 64 + b_) * 64 + hid4];
            float* dst = &sCH[(q * 4) * 65 + b_];
            dst[0]   = v.x;  dst[65]  = v.y;
            dst[130] = v.z;  dst[195] = v.w;
        }
        __syncthreads();
#pragma unroll 8
        for (int r = 0; r < 64; ++r)
            acc += sWo[n * 512 + ch * 64 + r] * sCH[r * 65 + bb];
    }
    g_logits[((size_t)t * 64 + bb) * 10 + n] = acc + sBo[n];
}

// ---------------------------------------------------------------------------
// Kernel D: Viterbi forward + backtrack. grid 64 (batch), 32 threads.
// ---------------------------------------------------------------------------
__global__ void viterbi_kernel(const float* __restrict__ trans,
                               float* __restrict__ out) {
    const int b = blockIdx.x, tid = threadIdx.x;
    __shared__ float tr[100];
    __shared__ float tA[10], tB[10];
    __shared__ unsigned char bp[512][10];

    for (int i = tid; i < 100; i += 32) tr[i] = trans[i];
    if (tid < 10) tA[tid] = g_logits[(size_t)(0 * 64 + b) * 10 + tid];
    __syncwarp();

    float* cur = tA;
    float* nxt = tB;
    float lt_next = (tid < 10) ? g_logits[(size_t)(1 * 64 + b) * 10 + tid] : 0.f;

    for (int t = 1; t < 512; ++t) {
        float lt = lt_next;
        if (t + 1 < 512 && tid < 10)
            lt_next = g_logits[(size_t)((t + 1) * 64 + b) * 10 + tid];
        if (tid < 10) {
            float best = cur[0] + tr[0 * 10 + tid];
            int bi = 0;
#pragma unroll
            for (int i = 1; i < 10; ++i) {
                float v = cur[i] + tr[i * 10 + tid];
                if (v > best) { best = v; bi = i; }
            }
            nxt[tid] = lt + best;
            bp[t][tid] = (unsigned char)bi;
        }
        __syncwarp();
        float* tmp = cur; cur = nxt; nxt = tmp;
    }

    if (tid == 0) {
        float best = cur[0]; int last = 0;
#pragma unroll
        for (int i = 1; i < 10; ++i) if (cur[i] > best) { best = cur[i]; last = i; }
        out[b] = best;
        float* po = out + 64 + (size_t)b * 512;
        int tag = last;
        po[511] = (float)tag;
        for (int t = 511; t >= 1; --t) {
            tag = bp[t][tag];
            po[t - 1] = (float)tag;
        }
    }
}

// ---------------------------------------------------------------------------
extern "C" void kernel_launch(void* const* d_in, const int* in_sizes, int n_in,
                              void* d_out, int out_size) {
    const int*   sent  = (const int*)  d_in[0];
    // d_in[1] = lengths (all == T, unused)
    const float* emb   = (const float*)d_in[2];
    const float* Wih_f = (const float*)d_in[3];
    const float* Whh_f = (const float*)d_in[4];
    const float* b_f   = (const float*)d_in[5];
    const float* Wih_b = (const float*)d_in[6];
    const float* Whh_b = (const float*)d_in[7];
    const float* b_b   = (const float*)d_in[8];
    const float* W_out = (const float*)d_in[9];
    const float* b_out = (const float*)d_in[10];
    const float* trans = (const float*)d_in[11];
    float* out = (float*)d_out;

    const size_t rec_smem = REC_SMEM_FLOATS * sizeof(float);  // 87360
    cudaFuncSetAttribute(lstm_rec_kernel,
                         cudaFuncAttributeMaxDynamicSharedMemorySize,
                         (int)rec_smem);

    init_kernel<<<1, 1>>>();
    pregemm_kernel<<<dim3(16, 512, 2), 256>>>(sent, emb, Wih_f, b_f, Wih_b, b_b);
    lstm_rec_kernel<<<128, 256, rec_smem>>>(Whh_f, Whh_b);
    logits_kernel<<<512, 640>>>(W_out, b_out);
    viterbi_kernel<<<64, 32>>>(trans, out);
}

// round 5
// speedup vs baseline: 1.0828x; 1.0828x over previous
#include <cuda_runtime.h>
#include <cuda_bf16.h>
#include <math.h>

// Problem constants
#define BB   64     // batch
#define TT   512    // time
#define EE   256    // embedding
#define HH   256    // hidden
#define G4   1024   // 4*H
#define KK   10     // tags

// -------- device scratch (allocation-free rule: static device globals) -----
__device__ float g_pre[2u * 32768u * 1024u];          // [dir][t*64+b][4H]
__device__ float g_h[2u * 512u * 64u * 256u];         // [dir][t][b][h]
__device__ float g_logits[512u * 64u * 10u];          // [t][b][k]

// -------- f32x2 packed helpers (used only where packing is free) -----------
__device__ __forceinline__ unsigned long long pk2(float x, float y) {
    unsigned long long r;
    asm("mov.b64 %0, {%1,%2};" : "=l"(r) : "f"(x), "f"(y));
    return r;
}
__device__ __forceinline__ void fma2(unsigned long long& d,
                                     unsigned long long a,
                                     unsigned long long b) {
    asm("fma.rn.f32x2 %0, %1, %2, %0;" : "+l"(d) : "l"(a), "l"(b));
}
__device__ __forceinline__ float2 up2(unsigned long long v) {
    float2 r;
    asm("mov.b64 {%0,%1}, %2;" : "=f"(r.x), "=f"(r.y) : "l"(v));
    return r;
}

__device__ __forceinline__ unsigned smem_u32(const void* p) {
    unsigned a;
    asm("{ .reg .u64 t; cvta.to.shared.u64 t, %1; cvt.u32.u64 %0, t; }"
        : "=r"(a) : "l"(p));
    return a;
}
__device__ __forceinline__ unsigned mapa_u32(unsigned laddr, unsigned peer) {
    unsigned r;
    asm("mapa.shared::cluster.u32 %0, %1, %2;" : "=r"(r) : "r"(laddr), "r"(peer));
    return r;
}
__device__ __forceinline__ void st_cluster_v4(unsigned addr, float4 v) {
    asm volatile("st.shared::cluster.v4.f32 [%0], {%1,%2,%3,%4};"
                 :: "r"(addr), "f"(v.x), "f"(v.y), "f"(v.z), "f"(v.w)
                 : "memory");
}

// ---------------------------------------------------------------------------
// Kernel A: fused embedding-gather + GEMM:  g_pre = emb[sent] @ Wih^T + bias
// (R3 plain-FFMA version — known good)
// ---------------------------------------------------------------------------
__global__ void pregemm_kernel(const int* __restrict__ sent,
                               const float* __restrict__ emb,
                               const float* __restrict__ Wih_f,
                               const float* __restrict__ b_f,
                               const float* __restrict__ Wih_b,
                               const float* __restrict__ b_b) {
    const int dir = blockIdx.z;
    const int t   = blockIdx.y;
    const int n0  = blockIdx.x * 64;
    const float* Wih  = dir ? Wih_b : Wih_f;
    const float* bias = dir ? b_b  : b_f;

    __shared__ float As[16][68];
    __shared__ float Bs[16][68];
    __shared__ int   toks[64];

    const int tid = threadIdx.x;          // 256 threads
    if (tid < 64) toks[tid] = sent[tid * TT + t];
    __syncthreads();

    const int mL = tid >> 2;
    const int kq = tid & 3;
    const int ty = tid >> 4;
    const int tx = tid & 15;

    float acc[4][4];
#pragma unroll
    for (int i = 0; i < 4; ++i)
#pragma unroll
        for (int j = 0; j < 4; ++j) acc[i][j] = 0.f;

    const float4* emb4 = (const float4*)emb;
    const float4* w4   = (const float4*)Wih;

    for (int k0 = 0; k0 < 256; k0 += 16) {
        float4 av = emb4[(size_t)toks[mL] * 64 + (k0 >> 2) + kq];
        float4 bv = w4[(size_t)(n0 + mL) * 64 + (k0 >> 2) + kq];
        __syncthreads();
        As[kq * 4 + 0][mL] = av.x;  As[kq * 4 + 1][mL] = av.y;
        As[kq * 4 + 2][mL] = av.z;  As[kq * 4 + 3][mL] = av.w;
        Bs[kq * 4 + 0][mL] = bv.x;  Bs[kq * 4 + 1][mL] = bv.y;
        Bs[kq * 4 + 2][mL] = bv.z;  Bs[kq * 4 + 3][mL] = bv.w;
        __syncthreads();
#pragma unroll
        for (int kk = 0; kk < 16; ++kk) {
            float4 a = *(const float4*)&As[kk][ty * 4];
            float4 b = *(const float4*)&Bs[kk][tx * 4];
            acc[0][0] += a.x * b.x; acc[0][1] += a.x * b.y; acc[0][2] += a.x * b.z; acc[0][3] += a.x * b.w;
            acc[1][0] += a.y * b.x; acc[1][1] += a.y * b.y; acc[1][2] += a.y * b.z; acc[1][3] += a.y * b.w;
            acc[2][0] += a.z * b.x; acc[2][1] += a.z * b.y; acc[2][2] += a.z * b.z; acc[2][3] += a.z * b.w;
            acc[3][0] += a.w * b.x; acc[3][1] += a.w * b.y; acc[3][2] += a.w * b.z; acc[3][3] += a.w * b.w;
        }
    }

    float4 bvv = ((const float4*)bias)[(n0 >> 2) + tx];
    float4* out4 = (float4*)g_pre;
#pragma unroll
    for (int i = 0; i < 4; ++i) {
        int b = ty * 4 + i;
        float4 o;
        o.x = acc[i][0] + bvv.x; o.y = acc[i][1] + bvv.y;
        o.z = acc[i][2] + bvv.z; o.w = acc[i][3] + bvv.w;
        out4[((size_t)dir * 32768 + (size_t)t * 64 + b) * 256 + (n0 >> 2) + tx] = o;
    }
}

// ---------------------------------------------------------------------------
// Kernel B: cluster-based recurrence. 16 independent clusters of 8 CTAs:
//   cluster = (dir, batch-group of 8);  CTA rank r owns hidden [r*32, r*32+32)
// Per step: each CTA computes its 32 units x 8 batches, pushes its 1KB h-slice
// into all 8 peers' smem (DSMEM), one barrier.cluster per step. No gmem h
// traffic, no global barrier.
//
// dyn smem (floats):
//   sW     : [4 gates][32 u][260 pitch]   = 33280 f  (133120 B)
//   sH     : [2 pp][8 b][268 pitch]       =  4288 f  ( 17152 B)
//   sStage : [8 b][32 u]                  =   256 f  (  1024 B)
// total 151296 B  -> 1 CTA/SM
// ---------------------------------------------------------------------------
#define SW_PITCH 260
#define SH_PITCH 268
#define OFF_SH   (4 * 32 * SW_PITCH)                  // floats
#define OFF_STG  (OFF_SH + 2 * 8 * SH_PITCH)          // floats
#define REC_SMEM_BYTES ((OFF_STG + 256) * 4)

__device__ __forceinline__ float sigm(float x) { return 1.f / (1.f + expf(-x)); }

__global__ void __cluster_dims__(8, 1, 1)
lstm_rec_kernel(const float* __restrict__ Whh_f,
                const float* __restrict__ Whh_b) {
    const int cid    = blockIdx.x >> 3;   // cluster id 0..15
    const int r      = blockIdx.x & 7;    // rank in cluster
    const int dir    = cid >> 3;
    const int bgroup = cid & 7;
    const int tid    = threadIdx.x;       // 256
    const int u      = tid >> 3;          // 0..31 local hidden unit
    const int bl     = tid & 7;           // 0..7 local batch
    const int bglob  = bgroup * 8 + bl;
    const int hu     = r * 32 + u;        // global hidden unit

    const float* Whh = dir ? Whh_b : Whh_f;

    extern __shared__ float sm[];
    float* sW   = sm;
    float* sH   = sm + OFF_SH;
    float* sStg = sm + OFF_STG;

    // load Whh slice: sW[g][u][k], pitch 260 (bank-skewed)
    const float4* whh4 = (const float4*)Whh;
    for (int e = tid; e < 8192; e += 256) {
        int g = e >> 11, rem = e & 2047, uu = rem >> 6, k4 = rem & 63;
        float4 v = whh4[(size_t)(g * 256 + r * 32 + uu) * 64 + k4];
        *(float4*)&sW[(g * 32 + uu) * SW_PITCH + k4 * 4] = v;
    }
    // zero sH ping buffer 0
    for (int e = tid; e < 8 * SH_PITCH; e += 256) sH[e] = 0.f;
    __syncthreads();

    // all cluster CTAs alive + smem initialized before any DSMEM traffic
    asm volatile("barrier.cluster.arrive.aligned;" ::: "memory");
    asm volatile("barrier.cluster.wait.aligned;" ::: "memory");

    const unsigned sh_base = smem_u32(sH);

    // weight row pointers for this thread's unit (16B-typed)
    const ulonglong2* w0 = (const ulonglong2*)&sW[(0 * 32 + u) * SW_PITCH];
    const ulonglong2* w1 = (const ulonglong2*)&sW[(1 * 32 + u) * SW_PITCH];
    const ulonglong2* w2 = (const ulonglong2*)&sW[(2 * 32 + u) * SW_PITCH];
    const ulonglong2* w3 = (const ulonglong2*)&sW[(3 * 32 + u) * SW_PITCH];

    // g_pre prefetch for first step
    const int t0 = dir ? 511 : 0;
    size_t pb = ((size_t)dir * 32768 + (size_t)t0 * 64 + bglob) * 1024 + hu;
    float4 pr;
    pr.x = __ldcg(&g_pre[pb]);
    pr.y = __ldcg(&g_pre[pb + 256]);
    pr.z = __ldcg(&g_pre[pb + 512]);
    pr.w = __ldcg(&g_pre[pb + 768]);

    float c = 0.f;

    for (int it = 0; it < 512; ++it) {
        const int t = dir ? (511 - it) : it;
        const int p = it & 1;

        unsigned long long a0 = pk2(pr.x, 0.f);
        unsigned long long a1 = pk2(pr.y, 0.f);
        unsigned long long a2 = pk2(pr.z, 0.f);
        unsigned long long a3 = pk2(pr.w, 0.f);

        // prefetch next step's g_pre (latency hidden under the k-loop)
        if (it < 511) {
            const int tn = dir ? (t - 1) : (t + 1);
            size_t pbn = ((size_t)dir * 32768 + (size_t)tn * 64 + bglob) * 1024 + hu;
            pr.x = __ldcg(&g_pre[pbn]);
            pr.y = __ldcg(&g_pre[pbn + 256]);
            pr.z = __ldcg(&g_pre[pbn + 512]);
            pr.w = __ldcg(&g_pre[pbn + 768]);
        }

        const ulonglong2* hrow = (const ulonglong2*)&sH[(p * 8 + bl) * SH_PITCH];

#pragma unroll 8
        for (int k4 = 0; k4 < 64; ++k4) {
            ulonglong2 h2 = hrow[k4];
            ulonglong2 w;
            w = w0[k4]; fma2(a0, w.x, h2.x); fma2(a0, w.y, h2.y);
            w = w1[k4]; fma2(a1, w.x, h2.x); fma2(a1, w.y, h2.y);
            w = w2[k4]; fma2(a2, w.x, h2.x); fma2(a2, w.y, h2.y);
            w = w3[k4]; fma2(a3, w.x, h2.x); fma2(a3, w.y, h2.y);
        }

        float2 q;
        q = up2(a0); float gi = q.x + q.y;
        q = up2(a1); float gf = q.x + q.y;
        q = up2(a2); float gg = q.x + q.y;
        q = up2(a3); float go = q.x + q.y;

        float iv = sigm(gi), fv = sigm(gf), gv = tanhf(gg), ov = sigm(go);
        c = fv * c + iv * gv;
        float hval = ov * tanhf(c);

        // h for logits kernel: [dir][t][b][h]
        g_h[(((size_t)(dir * 512 + t)) * 64 + bglob) * 256 + hu] = hval;

        // stage locally, then push to all 8 cluster CTAs' sH[p^1]
        sStg[bl * 32 + u] = hval;
        __syncthreads();

        if (it < 511) {
            const float4* stg4 = (const float4*)sStg;
#pragma unroll
            for (int e = tid; e < 512; e += 256) {
                int peer = e >> 6, f4i = e & 63;
                int bb = f4i >> 3, uq = f4i & 7;
                float4 v = stg4[f4i];
                unsigned laddr = sh_base
                               + (unsigned)(((p ^ 1) * 8 + bb) * SH_PITCH * 4)
                               + (unsigned)(r * 128 + uq * 16);
                st_cluster_v4(mapa_u32(laddr, (unsigned)peer), v);
            }
            asm volatile("barrier.cluster.arrive.aligned;" ::: "memory");
            asm volatile("barrier.cluster.wait.aligned;" ::: "memory");
        }
    }

    // final safety sync before any CTA of the cluster exits
    asm volatile("barrier.cluster.arrive.aligned;" ::: "memory");
    asm volatile("barrier.cluster.wait.aligned;" ::: "memory");
}

// ---------------------------------------------------------------------------
// Kernel C: logits = concat(h_f, h_b) @ W_out^T + b_out.  grid 512(t), 640 thr
// g_h layout [dir][t][b][h]; transpose chunks into sCH[r][b] (pitch 65).
// ---------------------------------------------------------------------------
__global__ void logits_kernel(const float* __restrict__ Wout,
                              const float* __restrict__ bout) {
    const int t = blockIdx.x;
    __shared__ float sWo[10 * 512];
    __shared__ float sCH[64 * 65];
    __shared__ float sBo[10];

    const int tid = threadIdx.x;      // 640
    for (int idx = tid; idx < 5120; idx += 640) sWo[idx] = Wout[idx];
    if (tid < 10) sBo[tid] = bout[tid];

    const int n = tid / 64, bb = tid & 63;
    float acc = 0.f;
    const float4* gh4 = (const float4*)g_h;

    for (int ch = 0; ch < 8; ++ch) {
        __syncthreads();
        for (int idx = tid; idx < 1024; idx += 640) {
            int b_ = idx >> 4, q = idx & 15;
            int d = ch >> 2;
            int hid4 = (ch & 3) * 16 + q;
            float4 v = gh4[(((size_t)d * 512 + t) * 64 + b_) * 64 + hid4];
            float* dst = &sCH[(q * 4) * 65 + b_];
            dst[0]   = v.x;  dst[65]  = v.y;
            dst[130] = v.z;  dst[195] = v.w;
        }
        __syncthreads();
#pragma unroll 8
        for (int r = 0; r < 64; ++r)
            acc += sWo[n * 512 + ch * 64 + r] * sCH[r * 65 + bb];
    }
    g_logits[((size_t)t * 64 + bb) * 10 + n] = acc + sBo[n];
}

// ---------------------------------------------------------------------------
// Kernel D: Viterbi forward + backtrack. grid 64 (batch), 32 threads.
// ---------------------------------------------------------------------------
__global__ void viterbi_kernel(const float* __restrict__ trans,
                               float* __restrict__ out) {
    const int b = blockIdx.x, tid = threadIdx.x;
    __shared__ float tr[100];
    __shared__ float tA[10], tB[10];
    __shared__ unsigned char bp[512][10];

    for (int i = tid; i < 100; i += 32) tr[i] = trans[i];
    if (tid < 10) tA[tid] = g_logits[(size_t)(0 * 64 + b) * 10 + tid];
    __syncwarp();

    float* cur = tA;
    float* nxt = tB;
    float lt_next = (tid < 10) ? g_logits[(size_t)(1 * 64 + b) * 10 + tid] : 0.f;

    for (int t = 1; t < 512; ++t) {
        float lt = lt_next;
        if (t + 1 < 512 && tid < 10)
            lt_next = g_logits[(size_t)((t + 1) * 64 + b) * 10 + tid];
        if (tid < 10) {
            float best = cur[0] + tr[0 * 10 + tid];
            int bi = 0;
#pragma unroll
            for (int i = 1; i < 10; ++i) {
                float v = cur[i] + tr[i * 10 + tid];
                if (v > best) { best = v; bi = i; }
            }
            nxt[tid] = lt + best;
            bp[t][tid] = (unsigned char)bi;
        }
        __syncwarp();
        float* tmp = cur; cur = nxt; nxt = tmp;
    }

    if (tid == 0) {
        float best = cur[0]; int last = 0;
#pragma unroll
        for (int i = 1; i < 10; ++i) if (cur[i] > best) { best = cur[i]; last = i; }
        out[b] = best;
        float* po = out + 64 + (size_t)b * 512;
        int tag = last;
        po[511] = (float)tag;
        for (int t = 511; t >= 1; --t) {
            tag = bp[t][tag];
            po[t - 1] = (float)tag;
        }
    }
}

// ---------------------------------------------------------------------------
extern "C" void kernel_launch(void* const* d_in, const int* in_sizes, int n_in,
                              void* d_out, int out_size) {
    const int*   sent  = (const int*)  d_in[0];
    // d_in[1] = lengths (all == T, unused)
    const float* emb   = (const float*)d_in[2];
    const float* Wih_f = (const float*)d_in[3];
    const float* Whh_f = (const float*)d_in[4];
    const float* b_f   = (const float*)d_in[5];
    const float* Wih_b = (const float*)d_in[6];
    const float* Whh_b = (const float*)d_in[7];
    const float* b_b   = (const float*)d_in[8];
    const float* W_out = (const float*)d_in[9];
    const float* b_out = (const float*)d_in[10];
    const float* trans = (const float*)d_in[11];
    float* out = (float*)d_out;

    cudaFuncSetAttribute(lstm_rec_kernel,
                         cudaFuncAttributeMaxDynamicSharedMemorySize,
                         REC_SMEM_BYTES);

    pregemm_kernel<<<dim3(16, 512, 2), 256>>>(sent, emb, Wih_f, b_f, Wih_b, b_b);
    lstm_rec_kernel<<<128, 256, REC_SMEM_BYTES>>>(Whh_f, Whh_b);
    logits_kernel<<<512, 640>>>(W_out, b_out);
    viterbi_kernel<<<64, 32>>>(trans, out);
}

// round 6
// speedup vs baseline: 1.1080x; 1.0233x over previous
#include <cuda_runtime.h>
#include <cuda_bf16.h>
#include <math.h>

// Problem constants
#define BB   64     // batch
#define TT   512    // time
#define EE   256    // embedding
#define HH   256    // hidden
#define G4   1024   // 4*H
#define KK   10     // tags

// -------- device scratch (allocation-free rule: static device globals) -----
__device__ float g_pre[2u * 32768u * 1024u];          // [dir][t*64+b][4H]
__device__ float g_h[2u * 512u * 64u * 256u];         // [dir][t][b][h]
__device__ float g_logits[512u * 64u * 10u];          // [t][b][k]

// -------- f32x2 packed helpers ----------------------------------------------
__device__ __forceinline__ unsigned long long pk2(float x, float y) {
    unsigned long long r;
    asm("mov.b64 %0, {%1,%2};" : "=l"(r) : "f"(x), "f"(y));
    return r;
}
__device__ __forceinline__ void fma2(unsigned long long& d,
                                     unsigned long long a,
                                     unsigned long long b) {
    asm("fma.rn.f32x2 %0, %1, %2, %0;" : "+l"(d) : "l"(a), "l"(b));
}
__device__ __forceinline__ float2 up2(unsigned long long v) {
    float2 r;
    asm("mov.b64 {%0,%1}, %2;" : "=f"(r.x), "=f"(r.y) : "l"(v));
    return r;
}

__device__ __forceinline__ unsigned smem_u32(const void* p) {
    unsigned a;
    asm("{ .reg .u64 t; cvta.to.shared.u64 t, %1; cvt.u32.u64 %0, t; }"
        : "=r"(a) : "l"(p));
    return a;
}
__device__ __forceinline__ unsigned mapa_u32(unsigned laddr, unsigned peer) {
    unsigned r;
    asm("mapa.shared::cluster.u32 %0, %1, %2;" : "=r"(r) : "r"(laddr), "r"(peer));
    return r;
}
__device__ __forceinline__ void st_cluster_v4(unsigned addr, float4 v) {
    asm volatile("st.shared::cluster.v4.f32 [%0], {%1,%2,%3,%4};"
                 :: "r"(addr), "f"(v.x), "f"(v.y), "f"(v.z), "f"(v.w)
                 : "memory");
}

// ---------------------------------------------------------------------------
// Kernel A: fused embedding-gather + GEMM:  g_pre = emb[sent] @ Wih^T + bias
// 128x128 tile, 8x8 per-thread microtile, double-buffered smem,
// one __syncthreads per 16-wide K chunk.
// grid (8 n-tiles, 256 m-tiles, 2 dirs), 256 threads.
// ---------------------------------------------------------------------------
__global__ void __launch_bounds__(256)
pregemm_kernel(const int* __restrict__ sent,
               const float* __restrict__ emb,
               const float* __restrict__ Wih_f,
               const float* __restrict__ b_f,
               const float* __restrict__ Wih_b,
               const float* __restrict__ b_b) {
    const int dir = blockIdx.z;
    const int n0  = blockIdx.x * 128;
    const int m0  = blockIdx.y * 128;
    const float* Wih  = dir ? Wih_b : Wih_f;
    const float* bias = dir ? b_b  : b_f;

    __shared__ float As[2][16][128];
    __shared__ float Bs[2][16][128];
    __shared__ int   toks[128];

    const int tid = threadIdx.x;
    if (tid < 128) {
        int m = m0 + tid;                 // m = t*64 + b
        toks[tid] = sent[(m & 63) * TT + (m >> 6)];
    }
    __syncthreads();

    const int mA   = tid & 127;
    const int half = tid >> 7;            // 0/1: which 8-k half this thread loads
    const int ty   = tid >> 4;             // 0..15 (m / 8)
    const int tx   = tid & 15;             // 0..15 (n / 8)

    const float4* emb4 = (const float4*)emb;
    const float4* w4   = (const float4*)Wih;

    const size_t arow = (size_t)toks[mA] * 64;      // float4 units per row
    const size_t brow = (size_t)(n0 + mA) * 64;

    float acc[8][8];
#pragma unroll
    for (int i = 0; i < 8; ++i)
#pragma unroll
        for (int j = 0; j < 8; ++j) acc[i][j] = 0.f;

    // load chunk 0 into regs
    float4 a0g = emb4[arow + half * 2 + 0];
    float4 a1g = emb4[arow + half * 2 + 1];
    float4 b0g = w4  [brow + half * 2 + 0];
    float4 b1g = w4  [brow + half * 2 + 1];

    int buf = 0;
    {
        const int kb = half * 8;
        As[0][kb+0][mA]=a0g.x; As[0][kb+1][mA]=a0g.y; As[0][kb+2][mA]=a0g.z; As[0][kb+3][mA]=a0g.w;
        As[0][kb+4][mA]=a1g.x; As[0][kb+5][mA]=a1g.y; As[0][kb+6][mA]=a1g.z; As[0][kb+7][mA]=a1g.w;
        Bs[0][kb+0][mA]=b0g.x; Bs[0][kb+1][mA]=b0g.y; Bs[0][kb+2][mA]=b0g.z; Bs[0][kb+3][mA]=b0g.w;
        Bs[0][kb+4][mA]=b1g.x; Bs[0][kb+5][mA]=b1g.y; Bs[0][kb+6][mA]=b1g.z; Bs[0][kb+7][mA]=b1g.w;
    }
    __syncthreads();

    for (int kc = 0; kc < 16; ++kc) {
        if (kc < 15) {
            const size_t kq = (size_t)(kc + 1) * 4 + half * 2;
            a0g = emb4[arow + kq];  a1g = emb4[arow + kq + 1];
            b0g = w4  [brow + kq];  b1g = w4  [brow + kq + 1];
        }
#pragma unroll
        for (int kk = 0; kk < 16; ++kk) {
            float4 aA = *(const float4*)&As[buf][kk][ty * 8];
            float4 aB = *(const float4*)&As[buf][kk][ty * 8 + 4];
            float4 bA = *(const float4*)&Bs[buf][kk][tx * 8];
            float4 bB = *(const float4*)&Bs[buf][kk][tx * 8 + 4];
            float av[8] = {aA.x, aA.y, aA.z, aA.w, aB.x, aB.y, aB.z, aB.w};
            float bv[8] = {bA.x, bA.y, bA.z, bA.w, bB.x, bB.y, bB.z, bB.w};
#pragma unroll
            for (int i = 0; i < 8; ++i)
#pragma unroll
                for (int j = 0; j < 8; ++j)
                    acc[i][j] += av[i] * bv[j];
        }
        if (kc < 15) {
            const int nb = buf ^ 1;
            const int kb = half * 8;
            As[nb][kb+0][mA]=a0g.x; As[nb][kb+1][mA]=a0g.y; As[nb][kb+2][mA]=a0g.z; As[nb][kb+3][mA]=a0g.w;
            As[nb][kb+4][mA]=a1g.x; As[nb][kb+5][mA]=a1g.y; As[nb][kb+6][mA]=a1g.z; As[nb][kb+7][mA]=a1g.w;
            Bs[nb][kb+0][mA]=b0g.x; Bs[nb][kb+1][mA]=b0g.y; Bs[nb][kb+2][mA]=b0g.z; Bs[nb][kb+3][mA]=b0g.w;
            Bs[nb][kb+4][mA]=b1g.x; Bs[nb][kb+5][mA]=b1g.y; Bs[nb][kb+6][mA]=b1g.z; Bs[nb][kb+7][mA]=b1g.w;
            __syncthreads();
            buf = nb;
        }
    }

    // epilogue: + bias, store 8x8
    float4 bv0 = ((const float4*)bias)[(n0 >> 2) + tx * 2];
    float4 bv1 = ((const float4*)bias)[(n0 >> 2) + tx * 2 + 1];
    float4* out4 = (float4*)g_pre;
#pragma unroll
    for (int i = 0; i < 8; ++i) {
        const int m = m0 + ty * 8 + i;
        const size_t row = (size_t)dir * 32768 + m;
        float4 o0, o1;
        o0.x = acc[i][0] + bv0.x; o0.y = acc[i][1] + bv0.y;
        o0.z = acc[i][2] + bv0.z; o0.w = acc[i][3] + bv0.w;
        o1.x = acc[i][4] + bv1.x; o1.y = acc[i][5] + bv1.y;
        o1.z = acc[i][6] + bv1.z; o1.w = acc[i][7] + bv1.w;
        out4[row * 256 + (n0 >> 2) + tx * 2]     = o0;
        out4[row * 256 + (n0 >> 2) + tx * 2 + 1] = o1;
    }
}

// ---------------------------------------------------------------------------
// Kernel B: cluster-based recurrence (unchanged from R5 — known passing).
// ---------------------------------------------------------------------------
#define SW_PITCH 260
#define SH_PITCH 268
#define OFF_SH   (4 * 32 * SW_PITCH)
#define OFF_STG  (OFF_SH + 2 * 8 * SH_PITCH)
#define REC_SMEM_BYTES ((OFF_STG + 256) * 4)

__device__ __forceinline__ float sigm(float x) { return 1.f / (1.f + expf(-x)); }

__global__ void __cluster_dims__(8, 1, 1)
lstm_rec_kernel(const float* __restrict__ Whh_f,
                const float* __restrict__ Whh_b) {
    const int cid    = blockIdx.x >> 3;
    const int r      = blockIdx.x & 7;
    const int dir    = cid >> 3;
    const int bgroup = cid & 7;
    const int tid    = threadIdx.x;       // 256
    const int u      = tid >> 3;
    const int bl     = tid & 7;
    const int bglob  = bgroup * 8 + bl;
    const int hu     = r * 32 + u;

    const float* Whh = dir ? Whh_b : Whh_f;

    extern __shared__ float sm[];
    float* sW   = sm;
    float* sH   = sm + OFF_SH;
    float* sStg = sm + OFF_STG;

    const float4* whh4 = (const float4*)Whh;
    for (int e = tid; e < 8192; e += 256) {
        int g = e >> 11, rem = e & 2047, uu = rem >> 6, k4 = rem & 63;
        float4 v = whh4[(size_t)(g * 256 + r * 32 + uu) * 64 + k4];
        *(float4*)&sW[(g * 32 + uu) * SW_PITCH + k4 * 4] = v;
    }
    for (int e = tid; e < 8 * SH_PITCH; e += 256) sH[e] = 0.f;
    __syncthreads();

    asm volatile("barrier.cluster.arrive.aligned;" ::: "memory");
    asm volatile("barrier.cluster.wait.aligned;" ::: "memory");

    const unsigned sh_base = smem_u32(sH);

    const ulonglong2* w0 = (const ulonglong2*)&sW[(0 * 32 + u) * SW_PITCH];
    const ulonglong2* w1 = (const ulonglong2*)&sW[(1 * 32 + u) * SW_PITCH];
    const ulonglong2* w2 = (const ulonglong2*)&sW[(2 * 32 + u) * SW_PITCH];
    const ulonglong2* w3 = (const ulonglong2*)&sW[(3 * 32 + u) * SW_PITCH];

    const int t0 = dir ? 511 : 0;
    size_t pb = ((size_t)dir * 32768 + (size_t)t0 * 64 + bglob) * 1024 + hu;
    float4 pr;
    pr.x = __ldcg(&g_pre[pb]);
    pr.y = __ldcg(&g_pre[pb + 256]);
    pr.z = __ldcg(&g_pre[pb + 512]);
    pr.w = __ldcg(&g_pre[pb + 768]);

    float c = 0.f;

    for (int it = 0; it < 512; ++it) {
        const int t = dir ? (511 - it) : it;
        const int p = it & 1;

        unsigned long long a0 = pk2(pr.x, 0.f);
        unsigned long long a1 = pk2(pr.y, 0.f);
        unsigned long long a2 = pk2(pr.z, 0.f);
        unsigned long long a3 = pk2(pr.w, 0.f);

        if (it < 511) {
            const int tn = dir ? (t - 1) : (t + 1);
            size_t pbn = ((size_t)dir * 32768 + (size_t)tn * 64 + bglob) * 1024 + hu;
            pr.x = __ldcg(&g_pre[pbn]);
            pr.y = __ldcg(&g_pre[pbn + 256]);
            pr.z = __ldcg(&g_pre[pbn + 512]);
            pr.w = __ldcg(&g_pre[pbn + 768]);
        }

        const ulonglong2* hrow = (const ulonglong2*)&sH[(p * 8 + bl) * SH_PITCH];

#pragma unroll 8
        for (int k4 = 0; k4 < 64; ++k4) {
            ulonglong2 h2 = hrow[k4];
            ulonglong2 w;
            w = w0[k4]; fma2(a0, w.x, h2.x); fma2(a0, w.y, h2.y);
            w = w1[k4]; fma2(a1, w.x, h2.x); fma2(a1, w.y, h2.y);
            w = w2[k4]; fma2(a2, w.x, h2.x); fma2(a2, w.y, h2.y);
            w = w3[k4]; fma2(a3, w.x, h2.x); fma2(a3, w.y, h2.y);
        }

        float2 q;
        q = up2(a0); float gi = q.x + q.y;
        q = up2(a1); float gf = q.x + q.y;
        q = up2(a2); float gg = q.x + q.y;
        q = up2(a3); float go = q.x + q.y;

        float iv = sigm(gi), fv = sigm(gf), gv = tanhf(gg), ov = sigm(go);
        c = fv * c + iv * gv;
        float hval = ov * tanhf(c);

        g_h[(((size_t)(dir * 512 + t)) * 64 + bglob) * 256 + hu] = hval;

        sStg[bl * 32 + u] = hval;
        __syncthreads();

        if (it < 511) {
            const float4* stg4 = (const float4*)sStg;
#pragma unroll
            for (int e = tid; e < 512; e += 256) {
                int peer = e >> 6, f4i = e & 63;
                int bb = f4i >> 3, uq = f4i & 7;
                float4 v = stg4[f4i];
                unsigned laddr = sh_base
                               + (unsigned)(((p ^ 1) * 8 + bb) * SH_PITCH * 4)
                               + (unsigned)(r * 128 + uq * 16);
                st_cluster_v4(mapa_u32(laddr, (unsigned)peer), v);
            }
            asm volatile("barrier.cluster.arrive.aligned;" ::: "memory");
            asm volatile("barrier.cluster.wait.aligned;" ::: "memory");
        }
    }

    asm volatile("barrier.cluster.arrive.aligned;" ::: "memory");
    asm volatile("barrier.cluster.wait.aligned;" ::: "memory");
}

// ---------------------------------------------------------------------------
// Kernel C: logits = concat(h_f, h_b) @ W_out^T + b_out.  grid 512(t), 640 thr
// ---------------------------------------------------------------------------
__global__ void logits_kernel(const float* __restrict__ Wout,
                              const float* __restrict__ bout) {
    const int t = blockIdx.x;
    __shared__ float sWo[10 * 512];
    __shared__ float sCH[64 * 65];
    __shared__ float sBo[10];

    const int tid = threadIdx.x;      // 640
    for (int idx = tid; idx < 5120; idx += 640) sWo[idx] = Wout[idx];
    if (tid < 10) sBo[tid] = bout[tid];

    const int n = tid / 64, bb = tid & 63;
    float acc = 0.f;
    const float4* gh4 = (const float4*)g_h;

    for (int ch = 0; ch < 8; ++ch) {
        __syncthreads();
        for (int idx = tid; idx < 1024; idx += 640) {
            int b_ = idx >> 4, q = idx & 15;
            int d = ch >> 2;
            int hid4 = (ch & 3) * 16 + q;
            float4 v = gh4[(((size_t)d * 512 + t) * 64 + b_) * 64 + hid4];
            float* dst = &sCH[(q * 4) * 65 + b_];
            dst[0]   = v.x;  dst[65]  = v.y;
            dst[130] = v.z;  dst[195] = v.w;
        }
        __syncthreads();
#pragma unroll 8
        for (int r = 0; r < 64; ++r)
            acc += sWo[n * 512 + ch * 64 + r] * sCH[r * 65 + bb];
    }
    g_logits[((size_t)t * 64 + bb) * 10 + n] = acc + sBo[n];
}

// ---------------------------------------------------------------------------
// Kernel D: Viterbi. grid 16 blocks x 128 threads (4 batches/block, 1 warp/b).
// Logits staged through smem in 16-step double-buffered chunks.
// ---------------------------------------------------------------------------
__global__ void viterbi_kernel(const float* __restrict__ trans,
                               float* __restrict__ out) {
    const int tid  = threadIdx.x;
    const int w    = tid >> 5;            // warp 0..3 -> batch
    const int lane = tid & 31;
    const int b    = blockIdx.x * 4 + w;

    __shared__ float         sLT[2][16][4][10];   // [buf][t][warp][tag]
    __shared__ float         sCur[4][32];
    __shared__ unsigned char bp[4][512][10];      // 20 KB
    __shared__ float         tr[100];

    for (int i = tid; i < 100; i += 128) tr[i] = trans[i];

    // chunk loader: chunk c covers t in [c*16, c*16+16)
    // 640 floats / 128 threads = 5 per thread
    const int bbase = blockIdx.x * 4;
    float stage[5];
#pragma unroll
    for (int s = 0; s < 5; ++s) {
        int idx = tid + s * 128;              // 0..639
        int t_off = idx / 40, rem = idx % 40;
        int b_off = rem / 10, k = rem % 10;
        stage[s] = g_logits[((size_t)(0 + t_off) * 64 + bbase + b_off) * 10 + k];
    }
#pragma unroll
    for (int s = 0; s < 5; ++s) {
        int idx = tid + s * 128;
        int t_off = idx / 40, rem = idx % 40;
        int b_off = rem / 10, k = rem % 10;
        sLT[0][t_off][b_off][k] = stage[s];
    }
    __syncthreads();

    float trc[10];
#pragma unroll
    for (int i = 0; i < 10; ++i) trc[i] = (lane < 10) ? tr[i * 10 + lane] : 0.f;

    float cur = (lane < 10) ? sLT[0][0][w][lane] : -1e30f;

    for (int cchunk = 0; cchunk < 32; ++cchunk) {
        const int buf = cchunk & 1;
        // prefetch next chunk (global loads issued early, consumed after 16 steps)
        if (cchunk < 31) {
            const int tb = (cchunk + 1) * 16;
#pragma unroll
            for (int s = 0; s < 5; ++s) {
                int idx = tid + s * 128;
                int t_off = idx / 40, rem = idx % 40;
                int b_off = rem / 10, k = rem % 10;
                stage[s] = g_logits[((size_t)(tb + t_off) * 64 + bbase + b_off) * 10 + k];
            }
        }

        const int tstart = (cchunk == 0) ? 1 : 0;   // t=0 consumed for init
#pragma unroll 4
        for (int ti = tstart; ti < 16; ++ti) {
            const int t = cchunk * 16 + ti;
            if (lane < 10) sCur[w][lane] = cur;
            __syncwarp();
            float best = sCur[w][0] + trc[0];
            int bi = 0;
#pragma unroll
            for (int i = 1; i < 10; ++i) {
                float v = sCur[w][i] + trc[i];
                if (v > best) { best = v; bi = i; }
            }
            __syncwarp();
            if (lane < 10) {
                cur = sLT[buf][ti][w][lane] + best;
                bp[w][t][lane] = (unsigned char)bi;
            }
        }

        if (cchunk < 31) {
            __syncthreads();                 // everyone done with buf^1
#pragma unroll
            for (int s = 0; s < 5; ++s) {
                int idx = tid + s * 128;
                int t_off = idx / 40, rem = idx % 40;
                int b_off = rem / 10, k = rem % 10;
                sLT[buf ^ 1][t_off][b_off][k] = stage[s];
            }
            __syncthreads();
        }
    }

    // final argmax + backtrack (lane 0 of each warp)
    if (lane < 10) sCur[w][lane] = cur;
    __syncwarp();
    if (lane == 0) {
        float best = sCur[w][0]; int last = 0;
#pragma unroll
        for (int i = 1; i < 10; ++i)
            if (sCur[w][i] > best) { best = sCur[w][i]; last = i; }
        out[b] = best;
        float* po = out + 64 + (size_t)b * 512;
        int tag = last;
        po[511] = (float)tag;
        for (int t = 511; t >= 1; --t) {
            tag = bp[w][t][tag];
            po[t - 1] = (float)tag;
        }
    }
}

// ---------------------------------------------------------------------------
extern "C" void kernel_launch(void* const* d_in, const int* in_sizes, int n_in,
                              void* d_out, int out_size) {
    const int*   sent  = (const int*)  d_in[0];
    // d_in[1] = lengths (all == T, unused)
    const float* emb   = (const float*)d_in[2];
    const float* Wih_f = (const float*)d_in[3];
    const float* Whh_f = (const float*)d_in[4];
    const float* b_f   = (const float*)d_in[5];
    const float* Wih_b = (const float*)d_in[6];
    const float* Whh_b = (const float*)d_in[7];
    const float* b_b   = (const float*)d_in[8];
    const float* W_out = (const float*)d_in[9];
    const float* b_out = (const float*)d_in[10];
    const float* trans = (const float*)d_in[11];
    float* out = (float*)d_out;

    cudaFuncSetAttribute(lstm_rec_kernel,
                         cudaFuncAttributeMaxDynamicSharedMemorySize,
                         REC_SMEM_BYTES);

    pregemm_kernel<<<dim3(8, 256, 2), 256>>>(sent, emb, Wih_f, b_f, Wih_b, b_b);
    lstm_rec_kernel<<<128, 256, REC_SMEM_BYTES>>>(Whh_f, Whh_b);
    logits_kernel<<<512, 640>>>(W_out, b_out);
    viterbi_kernel<<<16, 128>>>(trans, out);
}